// round 9
// baseline (speedup 1.0000x reference)
#include <cuda_runtime.h>

#define NDIM 4096

// Inter-layer spike vectors (scratch via __device__ globals — no allocation).
__device__ float g_enc[NDIM];
__device__ float g_s0[NDIM];
__device__ float g_s1[NDIM];

// Rate-coding encoder: enc_i = (u_i < x_i) ? 1 : 0.
__global__ void enc_k(const float* __restrict__ x, const float* __restrict__ u) {
    int i = blockIdx.x * blockDim.x + threadIdx.x;
    if (i < NDIM) g_enc[i] = (u[i] < x[i]) ? 1.0f : 0.0f;
}

// 256-bit global load (sm_100+): one LDG.E.256 = 32 B/lane, 1 KB/warp.
__device__ __forceinline__ void ldg256(const float* __restrict__ p, float r[8]) {
    unsigned u0, u1, u2, u3, u4, u5, u6, u7;
    asm volatile("ld.global.nc.v8.b32 {%0,%1,%2,%3,%4,%5,%6,%7}, [%8];"
                 : "=r"(u0), "=r"(u1), "=r"(u2), "=r"(u3),
                   "=r"(u4), "=r"(u5), "=r"(u6), "=r"(u7)
                 : "l"(p));
    r[0] = __uint_as_float(u0); r[1] = __uint_as_float(u1);
    r[2] = __uint_as_float(u2); r[3] = __uint_as_float(u3);
    r[4] = __uint_as_float(u4); r[5] = __uint_as_float(u5);
    r[6] = __uint_as_float(u6); r[7] = __uint_as_float(u7);
}

// Masked matvec + threshold. One row per block (grid 4096), 256 threads.
// Each thread: 2× v8 loads of W + 2× of M, all front-batched (4 KB/warp
// outstanding DRAM traffic), then FMA against the L1/L2-resident spike
// vector. Single shuffle+smem reduce at the end.
//  IN : 0 -> g_enc, 1 -> g_s0, 2 -> g_s1
//  OUT: 0 -> g_s0,  1 -> g_s1, 2 -> out[row] = spk / T
template<int IN, int OUT>
__global__ __launch_bounds__(256) void layer_k(const float* __restrict__ W,
                                               const float* __restrict__ M,
                                               const int* __restrict__ Tp,
                                               float* __restrict__ out) {
    const float* s = (IN == 0) ? g_enc : (IN == 1) ? g_s0 : g_s1;
    const int row = blockIdx.x;
    const float* __restrict__ wr = W + (size_t)row * NDIM;
    const float* __restrict__ mr = M + (size_t)row * NDIM;

    const int t8 = threadIdx.x * 8;            // chunk offsets: t8 and t8 + 2048

    // Front-batch all four 256-bit DRAM loads for this row.
    float w0[8], m0[8], w1[8], m1[8];
    ldg256(wr + t8,        w0);
    ldg256(mr + t8,        m0);
    ldg256(wr + 2048 + t8, w1);
    ldg256(mr + 2048 + t8, m1);

    const float4 va = __ldg((const float4*)(s + t8));
    const float4 vb = __ldg((const float4*)(s + t8) + 1);
    const float4 vc = __ldg((const float4*)(s + 2048 + t8));
    const float4 vd = __ldg((const float4*)(s + 2048 + t8) + 1);

    float a0 = 0.0f, a1 = 0.0f;
    a0 = fmaf(w0[0] * m0[0], va.x, a0); a0 = fmaf(w0[1] * m0[1], va.y, a0);
    a0 = fmaf(w0[2] * m0[2], va.z, a0); a0 = fmaf(w0[3] * m0[3], va.w, a0);
    a0 = fmaf(w0[4] * m0[4], vb.x, a0); a0 = fmaf(w0[5] * m0[5], vb.y, a0);
    a0 = fmaf(w0[6] * m0[6], vb.z, a0); a0 = fmaf(w0[7] * m0[7], vb.w, a0);
    a1 = fmaf(w1[0] * m1[0], vc.x, a1); a1 = fmaf(w1[1] * m1[1], vc.y, a1);
    a1 = fmaf(w1[2] * m1[2], vc.z, a1); a1 = fmaf(w1[3] * m1[3], vc.w, a1);
    a1 = fmaf(w1[4] * m1[4], vd.x, a1); a1 = fmaf(w1[5] * m1[5], vd.y, a1);
    a1 = fmaf(w1[6] * m1[6], vd.z, a1); a1 = fmaf(w1[7] * m1[7], vd.w, a1);

    float acc = a0 + a1;
#pragma unroll
    for (int o = 16; o; o >>= 1) acc += __shfl_xor_sync(0xffffffffu, acc, o);

    __shared__ float sm[8];
    if ((threadIdx.x & 31) == 0) sm[threadIdx.x >> 5] = acc;
    __syncthreads();

    if (threadIdx.x == 0) {
        float t = 0.0f;
#pragma unroll
        for (int i = 0; i < 8; i++) t += sm[i];
        const float spk = (t > 1.0f) ? 1.0f : 0.0f;   // THRESH = 1.0
        if (OUT == 0)      g_s0[row] = spk;
        else if (OUT == 1) g_s1[row] = spk;
        else {
            const int T = Tp ? *Tp : 128;
            out[row] = spk / (float)T;                // spikes only at t=0
        }
    }
}

extern "C" void kernel_launch(void* const* d_in, const int* in_sizes, int n_in,
                              void* d_out, int out_size) {
    const float* x  = (const float*)d_in[0];
    const float* u  = (const float*)d_in[1];
    const float* W0 = (const float*)d_in[2];
    const float* W1 = (const float*)d_in[3];
    const float* W2 = (const float*)d_in[4];
    const float* M0 = (const float*)d_in[5];
    const float* M1 = (const float*)d_in[6];
    const float* M2 = (const float*)d_in[7];
    const int*   T  = (n_in > 8) ? (const int*)d_in[8] : nullptr;
    float* out = (float*)d_out;

    enc_k<<<NDIM / 256, 256>>>(x, u);
    layer_k<0, 0><<<NDIM, 256>>>(W0, M0, nullptr, nullptr);
    layer_k<1, 1><<<NDIM, 256>>>(W1, M1, nullptr, nullptr);
    layer_k<2, 2><<<NDIM, 256>>>(W2, M2, T, out);
}

// round 10
// speedup vs baseline: 1.1551x; 1.1551x over previous
#include <cuda_runtime.h>
#include <cstdint>

#define NDIM 4096

// Inter-layer spike vectors (scratch via __device__ globals — no allocation).
__device__ float g_enc[NDIM];
__device__ float g_s0[NDIM];
__device__ float g_s1[NDIM];

// Rate-coding encoder: enc_i = (u_i < x_i) ? 1 : 0.
__global__ void enc_k(const float* __restrict__ x, const float* __restrict__ u) {
    int i = blockIdx.x * blockDim.x + threadIdx.x;
    if (i < NDIM) g_enc[i] = (u[i] < x[i]) ? 1.0f : 0.0f;
}

__device__ __forceinline__ uint32_t smem_u32(const void* p) {
    uint32_t a;
    asm("{ .reg .u64 t; cvta.to.shared.u64 t, %1; cvt.u32.u64 %0, t; }"
        : "=r"(a) : "l"(p));
    return a;
}
__device__ __forceinline__ void mbar_init(uint32_t a, uint32_t cnt) {
    asm volatile("mbarrier.init.shared.b64 [%0], %1;" :: "r"(a), "r"(cnt) : "memory");
}
__device__ __forceinline__ void mbar_expect_tx(uint32_t a, uint32_t bytes) {
    asm volatile("mbarrier.arrive.expect_tx.shared.b64 _, [%0], %1;"
                 :: "r"(a), "r"(bytes) : "memory");
}
// Plain (non-tensor) bulk copy global->shared, completion via mbarrier tx bytes.
__device__ __forceinline__ void bulk_g2s(uint32_t dst, const void* src,
                                         uint32_t bytes, uint32_t mbar) {
    asm volatile(
        "cp.async.bulk.shared::cta.global.mbarrier::complete_tx::bytes "
        "[%0], [%1], %2, [%3];"
        :: "r"(dst), "l"(src), "r"(bytes), "r"(mbar) : "memory");
}
__device__ __forceinline__ void mbar_wait(uint32_t a, uint32_t parity) {
    asm volatile(
        "{\n\t"
        ".reg .pred P;\n\t"
        "WAIT_%=: \n\t"
        "mbarrier.try_wait.parity.acquire.cta.shared::cta.b64 P, [%0], %1, 0x989680;\n\t"
        "@P bra.uni DONE_%=;\n\t"
        "bra.uni WAIT_%=;\n\t"
        "DONE_%=: \n\t"
        "}"
        :: "r"(a), "r"(parity) : "memory");
}

// Masked matvec + threshold. One row per block (grid 4096), 256 threads.
// W row + M row (16 KB each) land in smem via TWO cp.async.bulk copies
// (UBLKCP — bulk engine, zero LDG issue pressure). Warps sleep on the
// mbarrier, then FMA from smem against the L2-resident spike vector.
//  IN : 0 -> g_enc, 1 -> g_s0, 2 -> g_s1
//  OUT: 0 -> g_s0,  1 -> g_s1, 2 -> out[row] = spk / T
template<int IN, int OUT>
__global__ __launch_bounds__(256) void layer_k(const float* __restrict__ W,
                                               const float* __restrict__ M,
                                               const int* __restrict__ Tp,
                                               float* __restrict__ out) {
    __shared__ alignas(128) float sW[NDIM];    // 16 KB
    __shared__ alignas(128) float sM[NDIM];    // 16 KB
    __shared__ alignas(8) unsigned long long mbar_storage;
    __shared__ float red[8];

    const float* s = (IN == 0) ? g_enc : (IN == 1) ? g_s0 : g_s1;
    const int row = blockIdx.x;
    const uint32_t mbar = smem_u32(&mbar_storage);

    if (threadIdx.x == 0) mbar_init(mbar, 1);
    __syncthreads();

    if (threadIdx.x == 0) {
        mbar_expect_tx(mbar, 2u * NDIM * sizeof(float));  // 32 KB total
        bulk_g2s(smem_u32(sW), W + (size_t)row * NDIM, NDIM * sizeof(float), mbar);
        bulk_g2s(smem_u32(sM), M + (size_t)row * NDIM, NDIM * sizeof(float), mbar);
    }
    mbar_wait(mbar, 0);

    const float4* __restrict__ w4 = reinterpret_cast<const float4*>(sW);
    const float4* __restrict__ m4 = reinterpret_cast<const float4*>(sM);
    const float4* __restrict__ s4 = reinterpret_cast<const float4*>(s);

    float a0 = 0.0f, a1 = 0.0f;
#pragma unroll
    for (int k = 0; k < 4; k += 2) {
        const int i0 = threadIdx.x + (k + 0) * 256;
        const int i1 = threadIdx.x + (k + 1) * 256;
        const float4 w0 = w4[i0], m0 = m4[i0];
        const float4 w1 = w4[i1], m1 = m4[i1];
        const float4 v0 = __ldg(s4 + i0);
        const float4 v1 = __ldg(s4 + i1);
        a0 = fmaf(w0.x * m0.x, v0.x, a0);
        a0 = fmaf(w0.y * m0.y, v0.y, a0);
        a0 = fmaf(w0.z * m0.z, v0.z, a0);
        a0 = fmaf(w0.w * m0.w, v0.w, a0);
        a1 = fmaf(w1.x * m1.x, v1.x, a1);
        a1 = fmaf(w1.y * m1.y, v1.y, a1);
        a1 = fmaf(w1.z * m1.z, v1.z, a1);
        a1 = fmaf(w1.w * m1.w, v1.w, a1);
    }

    float acc = a0 + a1;
#pragma unroll
    for (int o = 16; o; o >>= 1) acc += __shfl_xor_sync(0xffffffffu, acc, o);

    if ((threadIdx.x & 31) == 0) red[threadIdx.x >> 5] = acc;
    __syncthreads();

    if (threadIdx.x == 0) {
        float t = 0.0f;
#pragma unroll
        for (int i = 0; i < 8; i++) t += red[i];
        const float spk = (t > 1.0f) ? 1.0f : 0.0f;   // THRESH = 1.0
        if (OUT == 0)      g_s0[row] = spk;
        else if (OUT == 1) g_s1[row] = spk;
        else {
            const int T = Tp ? *Tp : 128;
            out[row] = spk / (float)T;                // spikes only at t=0
        }
    }
}

extern "C" void kernel_launch(void* const* d_in, const int* in_sizes, int n_in,
                              void* d_out, int out_size) {
    const float* x  = (const float*)d_in[0];
    const float* u  = (const float*)d_in[1];
    const float* W0 = (const float*)d_in[2];
    const float* W1 = (const float*)d_in[3];
    const float* W2 = (const float*)d_in[4];
    const float* M0 = (const float*)d_in[5];
    const float* M1 = (const float*)d_in[6];
    const float* M2 = (const float*)d_in[7];
    const int*   T  = (n_in > 8) ? (const int*)d_in[8] : nullptr;
    float* out = (float*)d_out;

    enc_k<<<NDIM / 256, 256>>>(x, u);
    layer_k<0, 0><<<NDIM, 256>>>(W0, M0, nullptr, nullptr);
    layer_k<1, 1><<<NDIM, 256>>>(W1, M1, nullptr, nullptr);
    layer_k<2, 2><<<NDIM, 256>>>(W2, M2, T, out);
}